// round 6
// baseline (speedup 1.0000x reference)
#include <cuda_runtime.h>
#include <cstdint>

#define B_    64
#define T_    512
#define H_    1024
#define D_    512
#define GB_   4     // batch groups
#define CPG_  32    // CTAs (chunks) per group
#define BPG_  16    // batches per group
#define CHPC_ 32    // channels per CTA
#define NCTA_ (GB_*CPG_)
#define NTHR_ 512
#define SLOTS_ 4

// scratch (static __device__ arrays: zero at module load, allocation-free)
__device__ float  g_u[(size_t)T_ * B_ * H_];           // u drive [t][b][h]
__device__ float  g_stt[SLOTS_][B_][H_];               // state slots (depth 4)
__device__ int    g_flag[T_ + 1][GB_][CPG_];           // monotonic chunk-ready counters

// packed 2-wide fp32 FMA (sm_103a FFMA2, PTX-only)
__device__ __forceinline__ void fma2(unsigned long long& acc,
                                     unsigned long long a,
                                     unsigned long long b) {
    asm("fma.rn.f32x2 %0, %1, %2, %0;" : "+l"(acc) : "l"(a), "l"(b));
}
__device__ __forceinline__ float f2_lo(unsigned long long v) {
    return __uint_as_float((unsigned)(v & 0xffffffffull));
}
__device__ __forceinline__ float f2_hi(unsigned long long v) {
    return __uint_as_float((unsigned)(v >> 32));
}
__device__ __forceinline__ unsigned long long fdup(float x) {
    unsigned long long r;
    asm("mov.b64 %0, {%1, %1};" : "=l"(r) : "f"(x));
    return r;
}

// ---------------------------------------------------------------------------
// u[t][b][h] = sum_d x[b][t][d] * W_in[h][d] + b_in[h]  (f32x2 inner product)
// ---------------------------------------------------------------------------
__global__ __launch_bounds__(256) void u_gemm(const float* __restrict__ X,
                                              const float* __restrict__ Win,
                                              const float* __restrict__ bin) {
    __shared__ float As[8][128];
    __shared__ float Bs[8][128];
    int n0 = blockIdx.x * 128;
    int m0 = blockIdx.y * 128;
    int tid = threadIdx.x;
    int tm = tid >> 4, tn = tid & 15;

    unsigned long long acc2[8][4];
#pragma unroll
    for (int i = 0; i < 8; i++)
#pragma unroll
        for (int j = 0; j < 4; j++) acc2[i][j] = 0ull;

    int arow = tid >> 1;
    int ac4  = (tid & 1) * 4;
    const float* Aptr = X   + (size_t)(m0 + arow) * D_ + ac4;
    const float* Bptr = Win + (size_t)(n0 + arow) * D_ + ac4;

    for (int k0 = 0; k0 < D_; k0 += 8) {
        float4 av = *(const float4*)(Aptr + k0);
        float4 bv = *(const float4*)(Bptr + k0);
        As[ac4 + 0][arow] = av.x; As[ac4 + 1][arow] = av.y;
        As[ac4 + 2][arow] = av.z; As[ac4 + 3][arow] = av.w;
        Bs[ac4 + 0][arow] = bv.x; Bs[ac4 + 1][arow] = bv.y;
        Bs[ac4 + 2][arow] = bv.z; Bs[ac4 + 3][arow] = bv.w;
        __syncthreads();
#pragma unroll
        for (int kk = 0; kk < 8; kk++) {
            float rm[8];
            *(float4*)(rm)     = *(const float4*)&As[kk][tm * 8];
            *(float4*)(rm + 4) = *(const float4*)&As[kk][tm * 8 + 4];
            ulonglong2 t0 = *(const ulonglong2*)&Bs[kk][tn * 8];
            ulonglong2 t1 = *(const ulonglong2*)&Bs[kk][tn * 8 + 4];
            unsigned long long rnp[4] = {t0.x, t0.y, t1.x, t1.y};
#pragma unroll
            for (int i = 0; i < 8; i++) {
                unsigned long long rmd = fdup(rm[i]);
#pragma unroll
                for (int j = 0; j < 4; j++) fma2(acc2[i][j], rmd, rnp[j]);
            }
        }
        __syncthreads();
    }

    float bias[8];
    *(float4*)(bias)     = *(const float4*)&bin[n0 + tn * 8];
    *(float4*)(bias + 4) = *(const float4*)&bin[n0 + tn * 8 + 4];

#pragma unroll
    for (int i = 0; i < 8; i++) {
        int m  = m0 + tm * 8 + i;
        int tt = m & (T_ - 1);
        int bb = m >> 9;
        float* dst = g_u + ((size_t)tt * B_ + bb) * H_ + n0 + tn * 8;
        float4 v0, v1;
        v0.x = f2_lo(acc2[i][0]) + bias[0]; v0.y = f2_hi(acc2[i][0]) + bias[1];
        v0.z = f2_lo(acc2[i][1]) + bias[2]; v0.w = f2_hi(acc2[i][1]) + bias[3];
        v1.x = f2_lo(acc2[i][2]) + bias[4]; v1.y = f2_hi(acc2[i][2]) + bias[5];
        v1.z = f2_lo(acc2[i][3]) + bias[6]; v1.w = f2_hi(acc2[i][3]) + bias[7];
        *(float4*)(dst)     = v0;
        *(float4*)(dst + 4) = v1;
    }
}

// ---------------------------------------------------------------------------
// Persistent recurrence kernel, 512 threads/CTA.
// CTA (g,jc): batches [16g,16g+16), channels [32jc,32jc+32).
// 8 bricks of 8b x 8c; brick br = w>>1, K split by chunk parity kh = w&1.
// Lane (og=l>>3, kg=l&7): og -> 2 channels, kg -> K 8-way (float4 slices).
// s-loads broadcast across og (1 phase / 128B); balanced 4096/4096 floors.
// ---------------------------------------------------------------------------
__global__ __launch_bounds__(512, 1) void rec_kernel(
    const float* __restrict__ Wst, const float* __restrict__ bst,
    const float* __restrict__ decay, const float* __restrict__ gamma,
    const float* __restrict__ beta, float* __restrict__ out) {
    extern __shared__ float smem[];
    float* Wsm   = smem;                    // [32][1024] = 32768 floats
    float* Ssm   = smem + CHPC_ * H_;       // 2 bufs x [16][256] = 8192 floats
    float* pad   = Ssm + 2 * BPG_ * 256;    // [8 bricks][64] cross-warp partials
    float* bcast = pad + 512;               // [16]x{mean,rstd} + epoch at [33]

    int g   = blockIdx.x / CPG_;
    int jc  = blockIdx.x % CPG_;
    int ch0 = jc * CHPC_;
    int b0  = g * BPG_;
    int tid = threadIdx.x;
    int w = tid >> 5, l = tid & 31;
    int kh = w & 1, br = w >> 1;
    int og = l >> 3, kg = l & 7;

    // load W_state slice (rows ch0..ch0+31)
    {
        const float4* src = (const float4*)(Wst + (size_t)ch0 * H_);
        float4* dst = (float4*)Wsm;
        for (int v = tid; v < CHPC_ * H_ / 4; v += NTHR_) dst[v] = __ldg(src + v);
    }

    // output ownership (kh==0 lanes): batch b_loc = b0loc + kg, channels cl0, cl0+1
    int b0loc = (br & 1) * 8;
    int cl0   = (br >> 1) * 8 + og * 2;
    int b_loc = b0loc + kg;
    int gb    = b0 + b_loc;
    int mych  = ch0 + cl0;

    float dd0 = 1.0f / (1.0f + expf(-decay[mych]));
    float dd1 = 1.0f / (1.0f + expf(-decay[mych + 1]));
    float bs0 = bst[mych],   bs1 = bst[mych + 1];
    float ga0 = gamma[mych], ga1 = gamma[mych + 1];
    float be0 = beta[mych],  be1 = beta[mych + 1];
    const unsigned FULL = 0xffffffffu;

    // producer-chunk flag offsets for this thread's two staged float4 per group
    int pc0 = l >> 3;        // + 8*sg
    int pc1 = 4 + (l >> 3);  // + 8*sg

    const float* wbase = Wsm + cl0 * H_ + kg * 4;  // my channel row, my kg slice

    __syncthreads();

    float snp0 = 0.0f, snp1 = 0.0f;  // my 2 state values (kh==0), registers
    int target;                       // flag epoch target for this replay

    // ---------------- t = 0 : state is zero ----------------
    {
        if (kh == 0) {
            float2 uv = *(const float2*)(g_u + (size_t)gb * H_ + mych);
            snp0 = (1.0f - dd0) * tanhf(uv.x + bs0);
            snp1 = (1.0f - dd1) * tanhf(uv.y + bs1);
            __stcg((float2*)&g_stt[1][gb][mych], make_float2(snp0, snp1));
        }
        __threadfence();
        __syncthreads();
        if (tid == 0) {
            int old = atomicAdd(&g_flag[1][g][jc], 1);
            bcast[33] = __int_as_float(old + 1);
        }
        __syncthreads();
        target = __float_as_int(bcast[33]);
    }

    // ---------------- main loop t = 1..T-1 ----------------
    for (int t = 1; t < T_; ++t) {
        int slot  = t & 3;
        int wslot = (t + 1) & 3;
        float2 uv = make_float2(0.0f, 0.0f);
        if (kh == 0) uv = *(const float2*)(g_u + ((size_t)t * B_ + gb) * H_ + mych);

        unsigned long long acc[16];
#pragma unroll
        for (int o = 0; o < 16; o++) acc[o] = 0ull;

        float ln_s = 0.0f, ln_q = 0.0f;  // batch-w LN partials (loader role)
        const float4* srow = (const float4*)&g_stt[slot][b0][0];  // 256 f4/row

        // prologue: stage group seq(0)
        {
            int s0 = jc & 3;
            volatile int* f0 = &g_flag[t][g][8 * s0 + pc0];
            volatile int* f1 = &g_flag[t][g][8 * s0 + pc1];
            while (*f0 < target) {}
            while (*f1 < target) {}
            float4 r0 = __ldcg(&srow[w * 256 + s0 * 64 + l]);
            float4 r1 = __ldcg(&srow[w * 256 + s0 * 64 + l + 32]);
            ln_s += r0.x + r0.y + r0.z + r0.w + r1.x + r1.y + r1.z + r1.w;
            ln_q += r0.x*r0.x + r0.y*r0.y + r0.z*r0.z + r0.w*r0.w
                  + r1.x*r1.x + r1.y*r1.y + r1.z*r1.z + r1.w*r1.w;
            float4* d = (float4*)Ssm;
            d[w * 64 + l]      = r0;
            d[w * 64 + l + 32] = r1;
            __syncthreads();
        }

#pragma unroll
        for (int i = 0; i < 4; ++i) {
            int sg  = (i + jc) & 3;
            int buf = i & 1;
            float4 n0, n1;
            if (i < 3) {
                int sgn = (i + 1 + jc) & 3;
                volatile int* f0 = &g_flag[t][g][8 * sgn + pc0];
                volatile int* f1 = &g_flag[t][g][8 * sgn + pc1];
                while (*f0 < target) {}
                while (*f1 < target) {}
                n0 = __ldcg(&srow[w * 256 + sgn * 64 + l]);
                n1 = __ldcg(&srow[w * 256 + sgn * 64 + l + 32]);
                ln_s += n0.x + n0.y + n0.z + n0.w + n1.x + n1.y + n1.z + n1.w;
                ln_q += n0.x*n0.x + n0.y*n0.y + n0.z*n0.z + n0.w*n0.w
                      + n1.x*n1.x + n1.y*n1.y + n1.z*n1.z + n1.w*n1.w;
            }
            // GEMM on group sg from buffer buf: 4 parity chunks of 32 k
            {
                const float* sb = Ssm + buf * (BPG_ * 256) + b0loc * 256 + kg * 4;
                const float* wp = wbase + sg * 256;
#pragma unroll
                for (int j = 0; j < 4; j++) {
                    int kc = (2 * j + kh) * 32;
                    ulonglong2 wv0 = *(const ulonglong2*)(wp + kc);
                    ulonglong2 wv1 = *(const ulonglong2*)(wp + kc + H_);
#pragma unroll
                    for (int b = 0; b < 8; b++) {
                        ulonglong2 sv = *(const ulonglong2*)&sb[b * 256 + kc];
                        fma2(acc[b * 2 + 0], sv.x, wv0.x);
                        fma2(acc[b * 2 + 0], sv.y, wv0.y);
                        fma2(acc[b * 2 + 1], sv.x, wv1.x);
                        fma2(acc[b * 2 + 1], sv.y, wv1.y);
                    }
                }
            }
            if (i < 3) {
                float4* d = (float4*)(Ssm + (buf ^ 1) * (BPG_ * 256));
                d[w * 64 + l]      = n0;
                d[w * 64 + l + 32] = n1;
                __syncthreads();
            }
        }

        // collapse packed halves; 3-level butterfly over kg -> lane owns b=kg, c=0,1
        float accf[16];
#pragma unroll
        for (int o = 0; o < 16; o++) accf[o] = f2_lo(acc[o]) + f2_hi(acc[o]);
#pragma unroll
        for (int d = 4; d >= 1; d >>= 1) {
            int half = d * 2;  // surviving entries = 4d -> half = 2d
            bool up = (kg & d) != 0;
#pragma unroll
            for (int q = 0; q < half; q++) {
                float send = up ? accf[q] : accf[q + half];
                float recv = __shfl_xor_sync(FULL, send, d);
                accf[q] = (up ? accf[q + half] : accf[q]) + recv;
            }
        }

        // kh==1 publishes its K-half partials for the brick
        if (kh == 1) {
            pad[br * 64 + kg * 8 + og * 2 + 0] = accf[0];
            pad[br * 64 + kg * 8 + og * 2 + 1] = accf[1];
        }

        // LN stats for step t-1 (batch w), concurrent with pad publish
#pragma unroll
        for (int d = 16; d >= 1; d >>= 1) {
            ln_s += __shfl_xor_sync(FULL, ln_s, d);
            ln_q += __shfl_xor_sync(FULL, ln_q, d);
        }
        if (l == 0) {
            float mean = ln_s * (1.0f / H_);
            float var  = ln_q * (1.0f / H_) - mean * mean;
            bcast[w * 2 + 0] = mean;
            bcast[w * 2 + 1] = rsqrtf(var + 1e-5f);
        }
        __syncthreads();

        float sn0 = 0.0f, sn1 = 0.0f;
        if (kh == 0) {
            float2 oth = *(const float2*)&pad[br * 64 + kg * 8 + og * 2];
            float a0 = accf[0] + oth.x;
            float a1 = accf[1] + oth.y;
            float dr0 = tanhf(uv.x + a0 + bs0);
            float dr1 = tanhf(uv.y + a1 + bs1);
            sn0 = dd0 * snp0 + (1.0f - dd0) * dr0;
            sn1 = dd1 * snp1 + (1.0f - dd1) * dr1;
            __stcg((float2*)&g_stt[wslot][gb][mych], make_float2(sn0, sn1));
        }
        __threadfence();
        __syncthreads();
        if (tid == 0) atomicAdd(&g_flag[t + 1][g][jc], 1);

        // y(t-1) from register-resident snp
        if (kh == 0) {
            float mean = bcast[b_loc * 2 + 0], rstd = bcast[b_loc * 2 + 1];
            float2 yv;
            yv.x = (snp0 - mean) * rstd * ga0 + be0;
            yv.y = (snp1 - mean) * rstd * ga1 + be1;
            *(float2*)(out + ((size_t)gb * T_ + (t - 1)) * H_ + mych) = yv;
            snp0 = sn0; snp1 = sn1;
        }
    }

    // ---------------- final LayerNorm for t = T-1 (state in slot 0) ----------------
    {
        float ln_s = 0.0f, ln_q = 0.0f;
        const float4* srow = (const float4*)&g_stt[0][b0][0];
#pragma unroll
        for (int sg = 0; sg < 4; sg++) {
            volatile int* f0 = &g_flag[T_][g][8 * sg + pc0];
            volatile int* f1 = &g_flag[T_][g][8 * sg + pc1];
            while (*f0 < target) {}
            while (*f1 < target) {}
            float4 r0 = __ldcg(&srow[w * 256 + sg * 64 + l]);
            float4 r1 = __ldcg(&srow[w * 256 + sg * 64 + l + 32]);
            ln_s += r0.x + r0.y + r0.z + r0.w + r1.x + r1.y + r1.z + r1.w;
            ln_q += r0.x*r0.x + r0.y*r0.y + r0.z*r0.z + r0.w*r0.w
                  + r1.x*r1.x + r1.y*r1.y + r1.z*r1.z + r1.w*r1.w;
        }
#pragma unroll
        for (int d = 16; d >= 1; d >>= 1) {
            ln_s += __shfl_xor_sync(FULL, ln_s, d);
            ln_q += __shfl_xor_sync(FULL, ln_q, d);
        }
        if (l == 0) {
            float mean = ln_s * (1.0f / H_);
            float var  = ln_q * (1.0f / H_) - mean * mean;
            bcast[w * 2 + 0] = mean;
            bcast[w * 2 + 1] = rsqrtf(var + 1e-5f);
        }
        __syncthreads();
        if (kh == 0) {
            float mean = bcast[b_loc * 2 + 0], rstd = bcast[b_loc * 2 + 1];
            float2 yv;
            yv.x = (snp0 - mean) * rstd * ga0 + be0;
            yv.y = (snp1 - mean) * rstd * ga1 + be1;
            *(float2*)(out + ((size_t)gb * T_ + (T_ - 1)) * H_ + mych) = yv;
        }
    }
}

extern "C" void kernel_launch(void* const* d_in, const int* in_sizes, int n_in,
                              void* d_out, int out_size) {
    const float* x     = (const float*)d_in[0];
    const float* Win   = (const float*)d_in[1];
    const float* bin   = (const float*)d_in[2];
    const float* Wst   = (const float*)d_in[3];
    const float* bst   = (const float*)d_in[4];
    const float* decay = (const float*)d_in[5];
    const float* gamma = (const float*)d_in[6];
    const float* beta  = (const float*)d_in[7];
    float* out = (float*)d_out;

    const int smem_bytes = (CHPC_ * H_ + 2 * BPG_ * 256 + 512 + 40) * sizeof(float);
    cudaFuncSetAttribute(rec_kernel, cudaFuncAttributeMaxDynamicSharedMemorySize, smem_bytes);

    dim3 gg(H_ / 128, (B_ * T_) / 128);
    u_gemm<<<gg, 256>>>(x, Win, bin);
    rec_kernel<<<NCTA_, NTHR_, smem_bytes>>>(Wst, bst, decay, gamma, beta, out);
}

// round 7
// speedup vs baseline: 1.0277x; 1.0277x over previous
#include <cuda_runtime.h>
#include <cstdint>

#define B_    64
#define T_    512
#define H_    1024
#define D_    512
#define GB_   4     // batch groups
#define CPG_  32    // CTAs (chunks) per group
#define BPG_  16    // batches per group
#define CHPC_ 32    // channels per CTA
#define NCTA_ (GB_*CPG_)
#define NTHR_ 512
#define SLOTS_ 4

// scratch (static __device__ arrays: zero at module load, allocation-free)
__device__ float  g_u[(size_t)T_ * B_ * H_];           // u drive [t][b][h]
__device__ float  g_stt[SLOTS_][B_][H_];               // state slots (depth 4)
__device__ int    g_flag[T_ + 1][GB_][CPG_];           // monotonic counters (16/warp-arrivals per step)

// packed 2-wide fp32 FMA (sm_103a FFMA2, PTX-only)
__device__ __forceinline__ void fma2(unsigned long long& acc,
                                     unsigned long long a,
                                     unsigned long long b) {
    asm("fma.rn.f32x2 %0, %1, %2, %0;" : "+l"(acc) : "l"(a), "l"(b));
}
__device__ __forceinline__ float f2_lo(unsigned long long v) {
    return __uint_as_float((unsigned)(v & 0xffffffffull));
}
__device__ __forceinline__ float f2_hi(unsigned long long v) {
    return __uint_as_float((unsigned)(v >> 32));
}
__device__ __forceinline__ unsigned long long fdup(float x) {
    unsigned long long r;
    asm("mov.b64 %0, {%1, %1};" : "=l"(r) : "f"(x));
    return r;
}

// ---------------------------------------------------------------------------
// u[t][b][h] = sum_d x[b][t][d] * W_in[h][d] + b_in[h]  (f32x2 inner product)
// ---------------------------------------------------------------------------
__global__ __launch_bounds__(256) void u_gemm(const float* __restrict__ X,
                                              const float* __restrict__ Win,
                                              const float* __restrict__ bin) {
    __shared__ float As[8][128];
    __shared__ float Bs[8][128];
    int n0 = blockIdx.x * 128;
    int m0 = blockIdx.y * 128;
    int tid = threadIdx.x;
    int tm = tid >> 4, tn = tid & 15;

    unsigned long long acc2[8][4];
#pragma unroll
    for (int i = 0; i < 8; i++)
#pragma unroll
        for (int j = 0; j < 4; j++) acc2[i][j] = 0ull;

    int arow = tid >> 1;
    int ac4  = (tid & 1) * 4;
    const float* Aptr = X   + (size_t)(m0 + arow) * D_ + ac4;
    const float* Bptr = Win + (size_t)(n0 + arow) * D_ + ac4;

    for (int k0 = 0; k0 < D_; k0 += 8) {
        float4 av = *(const float4*)(Aptr + k0);
        float4 bv = *(const float4*)(Bptr + k0);
        As[ac4 + 0][arow] = av.x; As[ac4 + 1][arow] = av.y;
        As[ac4 + 2][arow] = av.z; As[ac4 + 3][arow] = av.w;
        Bs[ac4 + 0][arow] = bv.x; Bs[ac4 + 1][arow] = bv.y;
        Bs[ac4 + 2][arow] = bv.z; Bs[ac4 + 3][arow] = bv.w;
        __syncthreads();
#pragma unroll
        for (int kk = 0; kk < 8; kk++) {
            float rm[8];
            *(float4*)(rm)     = *(const float4*)&As[kk][tm * 8];
            *(float4*)(rm + 4) = *(const float4*)&As[kk][tm * 8 + 4];
            ulonglong2 t0 = *(const ulonglong2*)&Bs[kk][tn * 8];
            ulonglong2 t1 = *(const ulonglong2*)&Bs[kk][tn * 8 + 4];
            unsigned long long rnp[4] = {t0.x, t0.y, t1.x, t1.y};
#pragma unroll
            for (int i = 0; i < 8; i++) {
                unsigned long long rmd = fdup(rm[i]);
#pragma unroll
                for (int j = 0; j < 4; j++) fma2(acc2[i][j], rmd, rnp[j]);
            }
        }
        __syncthreads();
    }

    float bias[8];
    *(float4*)(bias)     = *(const float4*)&bin[n0 + tn * 8];
    *(float4*)(bias + 4) = *(const float4*)&bin[n0 + tn * 8 + 4];

#pragma unroll
    for (int i = 0; i < 8; i++) {
        int m  = m0 + tm * 8 + i;
        int tt = m & (T_ - 1);
        int bb = m >> 9;
        float* dst = g_u + ((size_t)tt * B_ + bb) * H_ + n0 + tn * 8;
        float4 v0, v1;
        v0.x = f2_lo(acc2[i][0]) + bias[0]; v0.y = f2_hi(acc2[i][0]) + bias[1];
        v0.z = f2_lo(acc2[i][1]) + bias[2]; v0.w = f2_hi(acc2[i][1]) + bias[3];
        v1.x = f2_lo(acc2[i][2]) + bias[4]; v1.y = f2_hi(acc2[i][2]) + bias[5];
        v1.z = f2_lo(acc2[i][3]) + bias[6]; v1.w = f2_hi(acc2[i][3]) + bias[7];
        *(float4*)(dst)     = v0;
        *(float4*)(dst + 4) = v1;
    }
}

// ---------------------------------------------------------------------------
// Persistent recurrence kernel, 512 threads/CTA (round-5 GEMM shape).
// CTA (g,jc): batches [16g,16g+16), channels [32jc,32jc+32).
// Warp w: 4 channels (cg=w&7) x 8 batches (bh=w>>3). Per-warp flag arrival:
// 16 atomics/step/chunk; LN folded into staging; y(t-1) written at i==3;
// tail has no __syncthreads (prologue sync of next step protects buffers).
// ---------------------------------------------------------------------------
__global__ __launch_bounds__(512, 1) void rec_kernel(
    const float* __restrict__ Wst, const float* __restrict__ bst,
    const float* __restrict__ decay, const float* __restrict__ gamma,
    const float* __restrict__ beta, float* __restrict__ out) {
    extern __shared__ float smem[];
    float* Wsm   = smem;                    // [32][1024] = 32768 floats
    float* Ssm   = smem + CHPC_ * H_;       // 2 bufs x [16][256] = 8192 floats
    float* bcast = Ssm + 2 * BPG_ * 256;    // [16]x{mean,rstd}

    int g   = blockIdx.x / CPG_;
    int jc  = blockIdx.x % CPG_;
    int ch0 = jc * CHPC_;
    int b0  = g * BPG_;
    int tid = threadIdx.x;
    int w = tid >> 5, l = tid & 31;
    int cg = w & 7, bh = w >> 3;

    // load W_state slice (rows ch0..ch0+31)
    {
        const float4* src = (const float4*)(Wst + (size_t)ch0 * H_);
        float4* dst = (float4*)Wsm;
        for (int v = tid; v < CHPC_ * H_ / 4; v += NTHR_) dst[v] = __ldg(src + v);
    }

    // output ownership: lane l owns acc index l -> batch bh*8 + (l>>2), channel cg*4 + (l&3)
    int myb  = bh * 8 + (l >> 2);
    int gb   = b0 + myb;
    int mych = ch0 + cg * 4 + (l & 3);

    float dd = 1.0f / (1.0f + expf(-decay[mych]));
    float bs = bst[mych];
    float ga = gamma[mych], be = beta[mych];
    const unsigned FULL = 0xffffffffu;

    // producer-chunk flag offsets for this thread's two staged float4 per group
    int pc0 = l >> 3;        // + 8*sg
    int pc1 = 4 + (l >> 3);  // + 8*sg

    const float* wb0 = Wsm + (cg * 4) * H_ + l * 4;  // channel row base

    __syncthreads();

    float snp;   // my state value (channel mych, batch gb), register-resident
    int thr;     // flag threshold for this replay (16 warp-arrivals per step)

    // ---------------- t = 0 : state is zero ----------------
    {
        float uv = __ldg(g_u + (size_t)gb * H_ + mych);
        snp = (1.0f - dd) * tanhf(uv + bs);
        __stcg(&g_stt[1][gb][mych], snp);
        __threadfence();
        int r = 0;
        if (l == 0) r = atomicAdd(&g_flag[1][g][jc], 1);
        r = __shfl_sync(FULL, r, 0);
        thr = (((r >> 4) + 1) << 4);   // = 16 * replay_number, identical across warps
    }

    // ---------------- main loop t = 1..T-1 ----------------
    for (int t = 1; t < T_; ++t) {
        int slot  = t & 3;
        int wslot = (t + 1) & 3;
        float uv = __ldg(g_u + ((size_t)t * B_ + gb) * H_ + mych);

        unsigned long long acc[32];
#pragma unroll
        for (int o = 0; o < 32; o++) acc[o] = 0ull;

        float ln_s = 0.0f, ln_q = 0.0f;  // batch-w LN partials (loader role)
        const float4* srow = (const float4*)&g_stt[slot][b0][0];  // 256 f4/row

        // prologue: stage group seq(0) into buf0
        {
            int s0 = jc & 3;
            volatile int* f0 = &g_flag[t][g][8 * s0 + pc0];
            volatile int* f1 = &g_flag[t][g][8 * s0 + pc1];
            while (*f0 < thr) {}
            while (*f1 < thr) {}
            float4 r0 = __ldcg(&srow[w * 256 + s0 * 64 + l]);
            float4 r1 = __ldcg(&srow[w * 256 + s0 * 64 + l + 32]);
            ln_s += r0.x + r0.y + r0.z + r0.w + r1.x + r1.y + r1.z + r1.w;
            ln_q += r0.x*r0.x + r0.y*r0.y + r0.z*r0.z + r0.w*r0.w
                  + r1.x*r1.x + r1.y*r1.y + r1.z*r1.z + r1.w*r1.w;
            float4* d = (float4*)Ssm;
            d[w * 64 + l]      = r0;
            d[w * 64 + l + 32] = r1;
            __syncthreads();
        }

#pragma unroll
        for (int i = 0; i < 4; ++i) {
            int sg  = (i + jc) & 3;
            int buf = i & 1;
            float4 n0, n1;
            if (i < 3) {
                int sgn = (i + 1 + jc) & 3;
                volatile int* f0 = &g_flag[t][g][8 * sgn + pc0];
                volatile int* f1 = &g_flag[t][g][8 * sgn + pc1];
                while (*f0 < thr) {}
                while (*f1 < thr) {}
                n0 = __ldcg(&srow[w * 256 + sgn * 64 + l]);
                n1 = __ldcg(&srow[w * 256 + sgn * 64 + l + 32]);
                ln_s += n0.x + n0.y + n0.z + n0.w + n1.x + n1.y + n1.z + n1.w;
                ln_q += n0.x*n0.x + n0.y*n0.y + n0.z*n0.z + n0.w*n0.w
                      + n1.x*n1.x + n1.y*n1.y + n1.z*n1.z + n1.w*n1.w;
            } else {
                // i == 3: bcast(t-1) published before i==2's sync -> safe to read.
                float mean = bcast[myb * 2 + 0], rstd = bcast[myb * 2 + 1];
                float y = (snp - mean) * rstd * ga + be;
                out[((size_t)gb * T_ + (t - 1)) * H_ + mych] = y;
            }
            // GEMM on group sg from buffer buf: two half-K passes
            {
                const float* sb = Ssm + buf * (BPG_ * 256) + bh * (8 * 256);
                const float* wp = wb0 + sg * 256;
#pragma unroll
                for (int half = 0; half < 2; half++) {
                    ulonglong2 wv0 = *(const ulonglong2*)(wp + half * 128);
                    ulonglong2 wv1 = *(const ulonglong2*)(wp + half * 128 + H_);
                    ulonglong2 wv2 = *(const ulonglong2*)(wp + half * 128 + 2 * H_);
                    ulonglong2 wv3 = *(const ulonglong2*)(wp + half * 128 + 3 * H_);
#pragma unroll
                    for (int b = 0; b < 8; b++) {
                        ulonglong2 sv = *(const ulonglong2*)&sb[b * 256 + half * 128 + l * 4];
                        fma2(acc[b * 4 + 0], sv.x, wv0.x);
                        fma2(acc[b * 4 + 0], sv.y, wv0.y);
                        fma2(acc[b * 4 + 1], sv.x, wv1.x);
                        fma2(acc[b * 4 + 1], sv.y, wv1.y);
                        fma2(acc[b * 4 + 2], sv.x, wv2.x);
                        fma2(acc[b * 4 + 2], sv.y, wv2.y);
                        fma2(acc[b * 4 + 3], sv.x, wv3.x);
                        fma2(acc[b * 4 + 3], sv.y, wv3.y);
                    }
                }
            }
            if (i < 3) {
                if (i == 2) {
                    // LN(t-1) complete: reduce + publish before the buffer-swap sync
#pragma unroll
                    for (int d = 16; d >= 1; d >>= 1) {
                        ln_s += __shfl_xor_sync(FULL, ln_s, d);
                        ln_q += __shfl_xor_sync(FULL, ln_q, d);
                    }
                    if (l == 0) {
                        float mean = ln_s * (1.0f / H_);
                        float var  = ln_q * (1.0f / H_) - mean * mean;
                        bcast[w * 2 + 0] = mean;
                        bcast[w * 2 + 1] = rsqrtf(var + 1e-5f);
                    }
                }
                float4* d = (float4*)(Ssm + (buf ^ 1) * (BPG_ * 256));
                d[w * 64 + l]      = n0;
                d[w * 64 + l + 32] = n1;
                __syncthreads();
            }
        }

        // tail (no block syncs): butterfly reduce -> update -> store -> flag
        float accf[32];
#pragma unroll
        for (int o = 0; o < 32; o++) accf[o] = f2_lo(acc[o]) + f2_hi(acc[o]);
#pragma unroll
        for (int delta = 16; delta >= 1; delta >>= 1) {
            bool up = (l & delta) != 0;
#pragma unroll
            for (int q = 0; q < delta; q++) {
                float send = up ? accf[q] : accf[q + delta];
                float recv = __shfl_xor_sync(FULL, send, delta);
                accf[q] = (up ? accf[q + delta] : accf[q]) + recv;
            }
        }

        float dr = tanhf(uv + accf[0] + bs);
        float sn = dd * snp + (1.0f - dd) * dr;
        __stcg(&g_stt[wslot][gb][mych], sn);
        __threadfence();
        if (l == 0) atomicAdd(&g_flag[t + 1][g][jc], 1);
        snp = sn;
    }

    // ---------------- final LayerNorm for t = T-1 (state in slot 0) ----------------
    {
        float ln_s = 0.0f, ln_q = 0.0f;
        const float4* srow = (const float4*)&g_stt[0][b0][0];
#pragma unroll
        for (int sg = 0; sg < 4; sg++) {
            volatile int* f0 = &g_flag[T_][g][8 * sg + pc0];
            volatile int* f1 = &g_flag[T_][g][8 * sg + pc1];
            while (*f0 < thr) {}
            while (*f1 < thr) {}
            float4 r0 = __ldcg(&srow[w * 256 + sg * 64 + l]);
            float4 r1 = __ldcg(&srow[w * 256 + sg * 64 + l + 32]);
            ln_s += r0.x + r0.y + r0.z + r0.w + r1.x + r1.y + r1.z + r1.w;
            ln_q += r0.x*r0.x + r0.y*r0.y + r0.z*r0.z + r0.w*r0.w
                  + r1.x*r1.x + r1.y*r1.y + r1.z*r1.z + r1.w*r1.w;
        }
#pragma unroll
        for (int d = 16; d >= 1; d >>= 1) {
            ln_s += __shfl_xor_sync(FULL, ln_s, d);
            ln_q += __shfl_xor_sync(FULL, ln_q, d);
        }
        if (l == 0) {
            float mean = ln_s * (1.0f / H_);
            float var  = ln_q * (1.0f / H_) - mean * mean;
            bcast[w * 2 + 0] = mean;
            bcast[w * 2 + 1] = rsqrtf(var + 1e-5f);
        }
        __syncthreads();
        float mean = bcast[myb * 2 + 0], rstd = bcast[myb * 2 + 1];
        float y = (snp - mean) * rstd * ga + be;
        out[((size_t)gb * T_ + (T_ - 1)) * H_ + mych] = y;
    }
}

extern "C" void kernel_launch(void* const* d_in, const int* in_sizes, int n_in,
                              void* d_out, int out_size) {
    const float* x     = (const float*)d_in[0];
    const float* Win   = (const float*)d_in[1];
    const float* bin   = (const float*)d_in[2];
    const float* Wst   = (const float*)d_in[3];
    const float* bst   = (const float*)d_in[4];
    const float* decay = (const float*)d_in[5];
    const float* gamma = (const float*)d_in[6];
    const float* beta  = (const float*)d_in[7];
    float* out = (float*)d_out;

    const int smem_bytes = (CHPC_ * H_ + 2 * BPG_ * 256 + 48) * sizeof(float);
    cudaFuncSetAttribute(rec_kernel, cudaFuncAttributeMaxDynamicSharedMemorySize, smem_bytes);

    dim3 gg(H_ / 128, (B_ * T_) / 128);
    u_gemm<<<gg, 256>>>(x, Win, bin);
    rec_kernel<<<NCTA_, NTHR_, smem_bytes>>>(Wst, bst, decay, gamma, beta, out);
}